// round 1
// baseline (speedup 1.0000x reference)
#include <cuda_runtime.h>
#include <cstdint>

// Problem constants: B=2, C=256, H=W=64 -> P=Q=4096, N=4, RADIUS=4 -> K2=81, 4 levels.
#define PQ   4096
#define KC   256
#define PYR  5440      // per-(b,p) pyramid floats: 4096 + 1024 + 256 + 64
#define PAD  136       // smem row stride (floats): 128 + 8 -> conflict-free frag loads

// Scratch pyramid: 2 * 4096 * 5440 floats = ~178 MB (device global; no runtime alloc).
__device__ float g_pyr[(size_t)2 * PQ * PYR];

__device__ __forceinline__ float to_tf32(float x) {
    uint32_t u;
    asm("cvt.rna.tf32.f32 %0, %1;" : "=r"(u) : "f"(x));
    return __uint_as_float(u);
}

__device__ __forceinline__ void mma_tf32(float d[4], const uint32_t a[4], const uint32_t b[2]) {
    asm volatile(
        "mma.sync.aligned.m16n8k8.row.col.f32.tf32.tf32.f32 "
        "{%0,%1,%2,%3}, {%4,%5,%6,%7}, {%8,%9}, {%0,%1,%2,%3};\n"
        : "+f"(d[0]), "+f"(d[1]), "+f"(d[2]), "+f"(d[3])
        : "r"(a[0]), "r"(a[1]), "r"(a[2]), "r"(a[3]), "r"(b[0]), "r"(b[1]));
}

// ---------------------------------------------------------------------------
// Stage 1: corr[b,p,q] = (1/16) * sum_c f1[b,c,p] * f2[b,c,q]
// f1/f2 are (C, PQ) per batch with PQ contiguous => operands are (K, M)/(K, N)
// with the M/N dim contiguous. Block tile 128x128, 4 warps (2x2 of 64x64),
// K-tile 16, double-buffered smem with register prefetch.
// Writes level-0 of the pyramid (row stride PYR).
// ---------------------------------------------------------------------------
__global__ __launch_bounds__(128) void gemm_corr(const float* __restrict__ f1,
                                                 const float* __restrict__ f2) {
    __shared__ float sA[2][16][PAD];
    __shared__ float sB[2][16][PAD];

    const int bz = blockIdx.z;
    const float* A  = f1 + (size_t)bz * KC * PQ;
    const float* Bg = f2 + (size_t)bz * KC * PQ;
    float* C = g_pyr + (size_t)bz * PQ * PYR;

    const int m0 = blockIdx.y * 128;
    const int n0 = blockIdx.x * 128;
    const int tid  = threadIdx.x;
    const int warp = tid >> 5, lane = tid & 31;
    const int wm = (warp & 1) * 64, wn = (warp >> 1) * 64;
    const int tg = lane >> 2, t4 = lane & 3;

    float acc[4][8][4];
#pragma unroll
    for (int i = 0; i < 4; i++)
#pragma unroll
        for (int j = 0; j < 8; j++)
#pragma unroll
            for (int q = 0; q < 4; q++) acc[i][j][q] = 0.f;

    // Global loader mapping: 16 rows x 128 floats per tile = 512 float4,
    // 128 threads x 4 float4 each, fully coalesced.
    int lk[4], lc[4];
#pragma unroll
    for (int r = 0; r < 4; r++) {
        int lin = r * 128 + tid;
        lk[r] = lin >> 5;
        lc[r] = (lin & 31) * 4;
    }

    float4 pa[4], pb[4];
#pragma unroll
    for (int r = 0; r < 4; r++) {
        pa[r] = *(const float4*)(A  + (size_t)lk[r] * PQ + m0 + lc[r]);
        pb[r] = *(const float4*)(Bg + (size_t)lk[r] * PQ + n0 + lc[r]);
    }
#pragma unroll
    for (int r = 0; r < 4; r++) {
        float4 a4 = pa[r], b4 = pb[r];
        *(float4*)&sA[0][lk[r]][lc[r]] =
            make_float4(to_tf32(a4.x), to_tf32(a4.y), to_tf32(a4.z), to_tf32(a4.w));
        *(float4*)&sB[0][lk[r]][lc[r]] =
            make_float4(to_tf32(b4.x), to_tf32(b4.y), to_tf32(b4.z), to_tf32(b4.w));
    }
    __syncthreads();

    for (int kt = 0; kt < 16; kt++) {
        const int buf = kt & 1;
        if (kt < 15) {
            const int kb = (kt + 1) * 16;
#pragma unroll
            for (int r = 0; r < 4; r++) {
                pa[r] = *(const float4*)(A  + (size_t)(kb + lk[r]) * PQ + m0 + lc[r]);
                pb[r] = *(const float4*)(Bg + (size_t)(kb + lk[r]) * PQ + n0 + lc[r]);
            }
        }
#pragma unroll
        for (int kk = 0; kk < 16; kk += 8) {
            uint32_t af[4][4], bf[8][2];
#pragma unroll
            for (int mt = 0; mt < 4; mt++) {
                const int mb = wm + mt * 16 + tg;
                af[mt][0] = __float_as_uint(sA[buf][kk + t4][mb]);
                af[mt][1] = __float_as_uint(sA[buf][kk + t4][mb + 8]);
                af[mt][2] = __float_as_uint(sA[buf][kk + t4 + 4][mb]);
                af[mt][3] = __float_as_uint(sA[buf][kk + t4 + 4][mb + 8]);
            }
#pragma unroll
            for (int nt = 0; nt < 8; nt++) {
                const int nb = wn + nt * 8 + tg;
                bf[nt][0] = __float_as_uint(sB[buf][kk + t4][nb]);
                bf[nt][1] = __float_as_uint(sB[buf][kk + t4 + 4][nb]);
            }
#pragma unroll
            for (int mt = 0; mt < 4; mt++)
#pragma unroll
                for (int nt = 0; nt < 8; nt++)
                    mma_tf32(acc[mt][nt], af[mt], bf[nt]);
        }
        if (kt < 15) {
            const int nb2 = buf ^ 1;
#pragma unroll
            for (int r = 0; r < 4; r++) {
                float4 a4 = pa[r], b4 = pb[r];
                *(float4*)&sA[nb2][lk[r]][lc[r]] =
                    make_float4(to_tf32(a4.x), to_tf32(a4.y), to_tf32(a4.z), to_tf32(a4.w));
                *(float4*)&sB[nb2][lk[r]][lc[r]] =
                    make_float4(to_tf32(b4.x), to_tf32(b4.y), to_tf32(b4.z), to_tf32(b4.w));
            }
            __syncthreads();
        }
    }

    // Epilogue: scale by 1/sqrt(C) = 1/16, write level-0 rows (stride PYR).
    const float sc = 0.0625f;
#pragma unroll
    for (int mt = 0; mt < 4; mt++) {
        const int m = m0 + wm + mt * 16 + tg;
#pragma unroll
        for (int nt = 0; nt < 8; nt++) {
            const int nc = n0 + wn + nt * 8 + t4 * 2;
            float2 v0 = make_float2(acc[mt][nt][0] * sc, acc[mt][nt][1] * sc);
            float2 v1 = make_float2(acc[mt][nt][2] * sc, acc[mt][nt][3] * sc);
            *(float2*)(C + (size_t)m * PYR + nc)       = v0;
            *(float2*)(C + (size_t)(m + 8) * PYR + nc) = v1;
        }
    }
}

// ---------------------------------------------------------------------------
// Stage 2: pyramid via 2x2 mean pooling, 3 levels. One block per (b,p).
// ---------------------------------------------------------------------------
__global__ __launch_bounds__(256) void pool_kernel() {
    const size_t bp = blockIdx.x;
    float* base = g_pyr + bp * PYR;
    const float* c0 = base;
    float* l1 = base + 4096;
    float* l2 = base + 5120;
    float* l3 = base + 5376;

    __shared__ float s1[1024];
    __shared__ float s2[256];
    const int t = threadIdx.x;

#pragma unroll
    for (int j = 0; j < 4; j++) {
        int i = t + j * 256;
        int y = i >> 5, x = i & 31;
        const float* r = c0 + y * 128 + x * 2;   // (2y)*64 + 2x
        float v = 0.25f * (r[0] + r[1] + r[64] + r[65]);
        s1[i] = v;
        l1[i] = v;
    }
    __syncthreads();
    {
        int y = t >> 4, x = t & 15;
        const float* r = s1 + y * 64 + x * 2;    // (2y)*32 + 2x
        float v = 0.25f * (r[0] + r[1] + r[32] + r[33]);
        s2[t] = v;
        l2[t] = v;
    }
    __syncthreads();
    if (t < 64) {
        int y = t >> 3, x = t & 7;
        const float* r = s2 + y * 32 + x * 2;    // (2y)*16 + 2x
        l3[t] = 0.25f * (r[0] + r[1] + r[16] + r[17]);
    }
}

// ---------------------------------------------------------------------------
// Stage 3: per-(b,n,p) lookup of 4 levels x 81 window samples, zero-padded
// bilinear. Faithful to the reference's delta swap: x gets d[k/9], y gets
// d[k%9]. Output layout: flat (B, N, P, 324) == (B, N*Ctot, H, W).
// ---------------------------------------------------------------------------
__global__ __launch_bounds__(128) void gather_kernel(const float* __restrict__ coords,
                                                     float* __restrict__ out) {
    const int idx = blockIdx.x;          // (b*4 + n) * 4096 + p
    const int p  = idx & 4095;
    const int bn = idx >> 12;
    const int b  = bn >> 2;
    const size_t bp = ((size_t)b << 12) | (size_t)p;

    const float cx = coords[((size_t)bn * 2)     * PQ + p];
    const float cy = coords[((size_t)bn * 2 + 1) * PQ + p];

    const float* pyr = g_pyr + bp * PYR;
    float* o = out + (size_t)idx * 324;

    for (int c = threadIdx.x; c < 324; c += blockDim.x) {
        const int l = c / 81;
        const int k = c - l * 81;
        const int dim  = 64 >> l;
        const float inv = 1.0f / (float)(1 << l);
        const int loff = (l == 0) ? 0 : (l == 1) ? 4096 : (l == 2) ? 5120 : 5376;
        const float* lv = pyr + loff;

        const int ki = k / 9;
        const float x = cx * inv + (float)(ki - 4);            // off_x = d[k/9]
        const float y = cy * inv + (float)(k - ki * 9 - 4);    // off_y = d[k%9]

        const float x0f = floorf(x), y0f = floorf(y);
        const int x0 = (int)x0f, y0 = (int)y0f;
        const float fx = x - x0f, fy = y - y0f;

        const bool xv0 = (x0 >= 0) && (x0 < dim);
        const bool xv1 = (x0 >= -1) && (x0 < dim - 1);
        const bool yv0 = (y0 >= 0) && (y0 < dim);
        const bool yv1 = (y0 >= -1) && (y0 < dim - 1);

        float v00 = 0.f, v01 = 0.f, v10 = 0.f, v11 = 0.f;
        const float* row0 = lv + y0 * dim;
        if (yv0) {
            if (xv0) v00 = row0[x0];
            if (xv1) v01 = row0[x0 + 1];
        }
        if (yv1) {
            if (xv0) v10 = row0[dim + x0];
            if (xv1) v11 = row0[dim + x0 + 1];
        }
        o[c] = (1.f - fy) * ((1.f - fx) * v00 + fx * v01)
             + fy         * ((1.f - fx) * v10 + fx * v11);
    }
}

extern "C" void kernel_launch(void* const* d_in, const int* in_sizes, int n_in,
                              void* d_out, int out_size) {
    const float* f1     = (const float*)d_in[0];   // (2, 256, 64, 64)
    const float* f2     = (const float*)d_in[1];   // (2, 256, 64, 64)
    const float* coords = (const float*)d_in[2];   // (2, 4, 2, 64, 64)
    float* out = (float*)d_out;                    // (2, 4*324, 64, 64)

    dim3 g(32, 32, 2);
    gemm_corr<<<g, 128>>>(f1, f2);
    pool_kernel<<<2 * PQ, 256>>>();
    gather_kernel<<<2 * 4 * PQ, 128>>>(coords, out);
}